// round 14
// baseline (speedup 1.0000x reference)
#include <cuda_runtime.h>

#define N_ENT  50000
#define C      128
#define N_RELM 10              // N_REL - 1
#define NKEY   (N_ENT * N_RELM)
#define EPS    1e-12f

// Scratch (no allocation allowed).
__device__ float          g_bufA[(size_t)N_ENT * C];
__device__ float          g_bufB[(size_t)N_ENT * C];
__device__ int            g_cnt[NKEY];        // (head,rel) histogram
__device__ int            g_fill[NKEY];       // mutable cursors
__device__ int            g_off[NKEY + 1];    // CSR offsets over (head,rel)
__device__ unsigned short g_tail[1600000];    // tails, sorted by (head,rel)

// ---------------------------------------------------------------------------
// Histogram over key = head*10 + (rel-1), 4 edges per thread (int4).
// ---------------------------------------------------------------------------
__global__ void hist_kernel(const int* __restrict__ edge_index,
                            const int* __restrict__ edge_type, int E4) {
    int i = blockIdx.x * blockDim.x + threadIdx.x;
    if (i >= E4) return;
    int4 h4 = __ldg(reinterpret_cast<const int4*>(edge_index) + i);
    int4 r4 = __ldg(reinterpret_cast<const int4*>(edge_type) + i);
    atomicAdd(&g_cnt[h4.x * N_RELM + (r4.x - 1)], 1);
    atomicAdd(&g_cnt[h4.y * N_RELM + (r4.y - 1)], 1);
    atomicAdd(&g_cnt[h4.z * N_RELM + (r4.z - 1)], 1);
    atomicAdd(&g_cnt[h4.w * N_RELM + (r4.w - 1)], 1);
}

// ---------------------------------------------------------------------------
// Single-block exclusive scan g_cnt -> g_off (NKEY entries); g_fill = copy.
// ---------------------------------------------------------------------------
__global__ void scan_kernel() {
    const int T = 1024;
    __shared__ int sh[T];
    int tid = threadIdx.x;
    const int chunk = (NKEY + T - 1) / T;
    int begin = tid * chunk;
    int endi  = begin + chunk; if (endi > NKEY) endi = NKEY;
    if (begin > NKEY) begin = NKEY;

    int sum = 0;
    for (int i = begin; i < endi; i++) sum += g_cnt[i];
    sh[tid] = sum;
    __syncthreads();
    for (int o = 1; o < T; o <<= 1) {
        int v = (tid >= o) ? sh[tid - o] : 0;
        __syncthreads();
        sh[tid] += v;
        __syncthreads();
    }
    int run = (tid == 0) ? 0 : sh[tid - 1];
    for (int i = begin; i < endi; i++) {
        g_off[i]  = run;
        g_fill[i] = run;
        run += g_cnt[i];
    }
    if (tid == T - 1) g_off[NKEY] = run;   // == E
}

// ---------------------------------------------------------------------------
// Scatter tails into (head,rel)-sorted order, 4 edges per thread.
// ---------------------------------------------------------------------------
__global__ void build_kernel(const int* __restrict__ edge_index,
                             const int* __restrict__ edge_type,
                             int E4, int E) {
    int i = blockIdx.x * blockDim.x + threadIdx.x;
    if (i >= E4) return;
    int4 h4 = __ldg(reinterpret_cast<const int4*>(edge_index) + i);
    int4 t4 = __ldg(reinterpret_cast<const int4*>(edge_index) + (E >> 2) + i);
    int4 r4 = __ldg(reinterpret_cast<const int4*>(edge_type) + i);
    int p0 = atomicAdd(&g_fill[h4.x * N_RELM + (r4.x - 1)], 1);
    int p1 = atomicAdd(&g_fill[h4.y * N_RELM + (r4.y - 1)], 1);
    int p2 = atomicAdd(&g_fill[h4.z * N_RELM + (r4.z - 1)], 1);
    int p3 = atomicAdd(&g_fill[h4.w * N_RELM + (r4.w - 1)], 1);
    g_tail[p0] = (unsigned short)t4.x;
    g_tail[p1] = (unsigned short)t4.y;
    g_tail[p2] = (unsigned short)t4.z;
    g_tail[p3] = (unsigned short)t4.w;
}

// ---------------------------------------------------------------------------
// One hop, fully fused: warp per head, no atomics, weight loaded ONCE per
// (head,rel) sub-segment (register-resident across the inner gather loop).
//   acc = mean over edges of emb_in[tail] * weight[rel]; L2-normalize;
//   emb_out[h] = acc; res[h] = (FIRST ? base[h] : res[h]) + acc.
// ---------------------------------------------------------------------------
template <bool FIRST>
__global__ void __launch_bounds__(256)
hop_kernel(const float* __restrict__ emb_in,
           const float* __restrict__ weight,
           float* __restrict__ emb_out,
           float* __restrict__ res,
           const float* __restrict__ base) {
    __shared__ float4 wsh[N_RELM * 32];   // 10 relations x 128 ch = 5 KB
    {
        float* wf = reinterpret_cast<float*>(wsh);
        for (int i = threadIdx.x; i < N_RELM * C; i += 256) wf[i] = weight[i];
    }
    __syncthreads();

    int head = blockIdx.x * 8 + (threadIdx.x >> 5);
    int lane = threadIdx.x & 31;
    if (head >= N_ENT) return;

    // Lane l (<11) holds offset of sub-segment l; broadcast via shfl.
    int kbase = head * N_RELM;
    int o_lane = 0;
    if (lane < N_RELM + 1) o_lane = g_off[kbase + lane];

    float4 acc = make_float4(0.f, 0.f, 0.f, 0.f);

    #pragma unroll 1
    for (int r = 0; r < N_RELM; r++) {
        int s  = __shfl_sync(0xffffffff, o_lane, r);
        int e1 = __shfl_sync(0xffffffff, o_lane, r + 1);
        if (e1 > s) {
            float4 wv = wsh[r * 32 + lane];   // one LDS per non-empty sub-segment
            int e = s;
            for (; e + 2 <= e1; e += 2) {     // 2x unroll: independent gathers
                int t0 = (int)g_tail[e];
                int t1 = (int)g_tail[e + 1];
                float4 v0 = __ldg(reinterpret_cast<const float4*>(emb_in + (size_t)t0 * C) + lane);
                float4 v1 = __ldg(reinterpret_cast<const float4*>(emb_in + (size_t)t1 * C) + lane);
                acc.x += v0.x * wv.x; acc.y += v0.y * wv.y;
                acc.z += v0.z * wv.z; acc.w += v0.w * wv.w;
                acc.x += v1.x * wv.x; acc.y += v1.y * wv.y;
                acc.z += v1.z * wv.z; acc.w += v1.w * wv.w;
            }
            for (; e < e1; e++) {
                int t = (int)g_tail[e];
                float4 v = __ldg(reinterpret_cast<const float4*>(emb_in + (size_t)t * C) + lane);
                acc.x += v.x * wv.x; acc.y += v.y * wv.y;
                acc.z += v.z * wv.z; acc.w += v.w * wv.w;
            }
        }
    }

    // scatter_mean over the whole head segment
    int deg = __shfl_sync(0xffffffff, o_lane, N_RELM) -
              __shfl_sync(0xffffffff, o_lane, 0);
    float inv_d = 1.0f / fmaxf((float)deg, 1.0f);
    acc.x *= inv_d; acc.y *= inv_d; acc.z *= inv_d; acc.w *= inv_d;

    // L2 normalize
    float s2 = acc.x * acc.x + acc.y * acc.y + acc.z * acc.z + acc.w * acc.w;
    #pragma unroll
    for (int o = 16; o > 0; o >>= 1) s2 += __shfl_xor_sync(0xffffffff, s2, o);
    float inv_n = 1.0f / fmaxf(sqrtf(s2), EPS);
    acc.x *= inv_n; acc.y *= inv_n; acc.z *= inv_n; acc.w *= inv_n;

    // next-hop input
    reinterpret_cast<float4*>(emb_out + (size_t)head * C)[lane] = acc;

    // res accumulate
    float4* rrow = reinterpret_cast<float4*>(res + (size_t)head * C);
    float4 o4;
    if (FIRST) {
        o4 = __ldg(reinterpret_cast<const float4*>(base + (size_t)head * C) + lane);
    } else {
        o4 = rrow[lane];
    }
    o4.x += acc.x; o4.y += acc.y; o4.z += acc.z; o4.w += acc.w;
    rrow[lane] = o4;
}

// ---------------------------------------------------------------------------
// kernel_launch
// Inputs: entity_emb f32 [50000,128], edge_index i32 [2,E],
//         edge_type i32 [E], weight f32 [10,128]
// Output: f32 [50000,128]
// ---------------------------------------------------------------------------
extern "C" void kernel_launch(void* const* d_in, const int* in_sizes, int n_in,
                              void* d_out, int out_size) {
    const float* emb = (const float*)d_in[0];
    const int*   ei  = (const int*)d_in[1];
    const int*   et  = (const int*)d_in[2];
    const float* w   = (const float*)d_in[3];
    float* out = (float*)d_out;

    const int E  = in_sizes[1] / 2;
    const int E4 = E / 4;              // E = 1.6M, divisible by 4

    void *pA = nullptr, *pB = nullptr, *pC = nullptr;
    cudaGetSymbolAddress(&pA, g_bufA);
    cudaGetSymbolAddress(&pB, g_bufB);
    cudaGetSymbolAddress(&pC, g_cnt);
    float* A = (float*)pA;
    float* B = (float*)pB;

    // ---- Build (head,rel)-sorted CSR (once; reused by all 3 hops) ----
    cudaMemsetAsync(pC, 0, NKEY * sizeof(int));
    hist_kernel<<<(E4 + 255) / 256, 256>>>(ei, et, E4);
    scan_kernel<<<1, 1024>>>();
    build_kernel<<<(E4 + 255) / 256, 256>>>(ei, et, E4, E);

    // ---- 3 fused hops (hop 1 folds res = emb + n1) ----
    const int HOP_BLOCKS = (N_ENT + 7) / 8;   // warp per head, 8 warps/block
    hop_kernel<true ><<<HOP_BLOCKS, 256>>>(emb, w, A, out, emb);  // emb -> A
    hop_kernel<false><<<HOP_BLOCKS, 256>>>(A,   w, B, out, emb);  // A -> B
    hop_kernel<false><<<HOP_BLOCKS, 256>>>(B,   w, A, out, emb);  // B -> A
}

// round 16
// speedup vs baseline: 4.2839x; 4.2839x over previous
#include <cuda_runtime.h>

#define N_ENT  50000
#define C      128
#define N_RELM 10              // N_REL - 1
#define EPS    1e-12f
#define NTILE  ((N_ENT + 255) / 256)   // scan tiles (196)

// Scratch (no allocation allowed).
__device__ float    g_bufA[(size_t)N_ENT * C];   // n1
__device__ float    g_bufB[(size_t)N_ENT * C];   // n2
__device__ int      g_cnt[N_ENT];
__device__ int      g_fill[N_ENT];
__device__ int      g_off[N_ENT + 1];
__device__ int      g_bsum[NTILE];
__device__ unsigned g_sorted[1600000];           // tail | (rel << 16)

// ---------------------------------------------------------------------------
// Histogram of heads, 4 edges per thread (int4) for MLP on the atomics.
// ---------------------------------------------------------------------------
__global__ void hist_kernel(const int* __restrict__ edge_index, int E4, int E) {
    int i = blockIdx.x * blockDim.x + threadIdx.x;
    if (i < E4) {
        int4 h4 = __ldg(reinterpret_cast<const int4*>(edge_index) + i);
        atomicAdd(&g_cnt[h4.x], 1);
        atomicAdd(&g_cnt[h4.y], 1);
        atomicAdd(&g_cnt[h4.z], 1);
        atomicAdd(&g_cnt[h4.w], 1);
    } else if (i == E4) {                 // remainder (E % 4 edges)
        for (int e = E4 * 4; e < E; e++) atomicAdd(&g_cnt[edge_index[e]], 1);
    }
}

// ---------------------------------------------------------------------------
// Parallel scan, step 1: per-tile (256 elems) sums. Coalesced.
// ---------------------------------------------------------------------------
__global__ void tile_sum_kernel() {
    int i = blockIdx.x * 256 + threadIdx.x;
    int v = (i < N_ENT) ? g_cnt[i] : 0;
    #pragma unroll
    for (int o = 16; o > 0; o >>= 1) v += __shfl_xor_sync(0xffffffff, v, o);
    __shared__ int ws[8];
    if ((threadIdx.x & 31) == 0) ws[threadIdx.x >> 5] = v;
    __syncthreads();
    if (threadIdx.x == 0) {
        int s = 0;
        #pragma unroll
        for (int w = 0; w < 8; w++) s += ws[w];
        g_bsum[blockIdx.x] = s;
    }
}

// ---------------------------------------------------------------------------
// Parallel scan, step 2: single block exclusive-scans the NTILE block sums
// in place; writes g_off[N_ENT] = total (== E).
// ---------------------------------------------------------------------------
__global__ void bsum_scan_kernel() {
    __shared__ int sh[256];
    int tid = threadIdx.x;
    int v = (tid < NTILE) ? g_bsum[tid] : 0;
    int lane = tid & 31, wid = tid >> 5;
    int x = v;
    #pragma unroll
    for (int o = 1; o < 32; o <<= 1) {
        int y = __shfl_up_sync(0xffffffff, x, o);
        if (lane >= o) x += y;
    }
    __shared__ int ws[8];
    if (lane == 31) ws[wid] = x;
    __syncthreads();
    if (tid == 0) {
        int run = 0;
        #pragma unroll
        for (int w = 0; w < 8; w++) { int t = ws[w]; ws[w] = run; run += t; }
        sh[255] = run;   // total
    }
    __syncthreads();
    int excl = x - v + ws[wid];
    if (tid < NTILE) g_bsum[tid] = excl;
    if (tid == 0) g_off[N_ENT] = sh[255];
}

// ---------------------------------------------------------------------------
// Parallel scan, step 3: per-tile exclusive scan + tile offset -> g_off/g_fill.
// ---------------------------------------------------------------------------
__global__ void tile_scan_kernel() {
    int i = blockIdx.x * 256 + threadIdx.x;
    int v = (i < N_ENT) ? g_cnt[i] : 0;
    int lane = threadIdx.x & 31, wid = threadIdx.x >> 5;
    int x = v;
    #pragma unroll
    for (int o = 1; o < 32; o <<= 1) {
        int y = __shfl_up_sync(0xffffffff, x, o);
        if (lane >= o) x += y;
    }
    __shared__ int ws[8];
    if (lane == 31) ws[wid] = x;
    __syncthreads();
    if (threadIdx.x == 0) {
        int run = 0;
        #pragma unroll
        for (int w = 0; w < 8; w++) { int t = ws[w]; ws[w] = run; run += t; }
    }
    __syncthreads();
    int off = g_bsum[blockIdx.x] + ws[wid] + (x - v);
    if (i < N_ENT) { g_off[i] = off; g_fill[i] = off; }
}

// ---------------------------------------------------------------------------
// Scatter edges into head-sorted order, 4 edges per thread.
// Packs (tail, rel) into one uint: tail < 65536; rel in [0,9].
// ---------------------------------------------------------------------------
__global__ void build_kernel(const int* __restrict__ edge_index,
                             const int* __restrict__ edge_type,
                             int E4, int E) {
    int i = blockIdx.x * blockDim.x + threadIdx.x;
    if (i < E4) {
        int4 h4 = __ldg(reinterpret_cast<const int4*>(edge_index) + i);
        int4 t4 = __ldg(reinterpret_cast<const int4*>(edge_index) + (E >> 2) + i);
        int4 r4 = __ldg(reinterpret_cast<const int4*>(edge_type) + i);
        int p0 = atomicAdd(&g_fill[h4.x], 1);
        int p1 = atomicAdd(&g_fill[h4.y], 1);
        int p2 = atomicAdd(&g_fill[h4.z], 1);
        int p3 = atomicAdd(&g_fill[h4.w], 1);
        g_sorted[p0] = (unsigned)t4.x | ((unsigned)(r4.x - 1) << 16);
        g_sorted[p1] = (unsigned)t4.y | ((unsigned)(r4.y - 1) << 16);
        g_sorted[p2] = (unsigned)t4.z | ((unsigned)(r4.z - 1) << 16);
        g_sorted[p3] = (unsigned)t4.w | ((unsigned)(r4.w - 1) << 16);
    } else if (i == E4) {
        for (int e = E4 * 4; e < E; e++) {
            int h = edge_index[e];
            int p = atomicAdd(&g_fill[h], 1);
            g_sorted[p] = (unsigned)edge_index[E + e] |
                          ((unsigned)(edge_type[e] - 1) << 16);
        }
    }
}

// ---------------------------------------------------------------------------
// One hop: warp per head, no atomics.
//   acc = mean over segment of emb_in[tail] * weight[rel]; L2-normalize.
//   !FINAL: emb_out[h] = acc                      (n1 / n2 buffers)
//   FINAL : res[h] = base[h] + n1[h] + n2[h] + acc (skips emb_out store)
// ---------------------------------------------------------------------------
template <bool FINAL>
__global__ void __launch_bounds__(256)
hop_kernel(const float* __restrict__ emb_in,
           const float* __restrict__ weight,
           float* __restrict__ emb_out,
           float* __restrict__ res,
           const float* __restrict__ base,
           const float* __restrict__ n1,
           const float* __restrict__ n2) {
    __shared__ float4 wsh[N_RELM * 32];   // 10 relations x 128 ch = 5 KB
    {
        float* wf = reinterpret_cast<float*>(wsh);
        for (int i = threadIdx.x; i < N_RELM * C; i += 256) wf[i] = weight[i];
    }
    __syncthreads();

    int head = blockIdx.x * 8 + (threadIdx.x >> 5);
    int lane = threadIdx.x & 31;
    if (head >= N_ENT) return;

    int start = g_off[head];
    int end   = g_off[head + 1];

    // two accumulators to halve the FFMA dependency chain
    float4 accA = make_float4(0.f, 0.f, 0.f, 0.f);
    float4 accB = make_float4(0.f, 0.f, 0.f, 0.f);

    int e = start;
    for (; e + 4 <= end; e += 4) {
        unsigned p0 = g_sorted[e + 0];
        unsigned p1 = g_sorted[e + 1];
        unsigned p2 = g_sorted[e + 2];
        unsigned p3 = g_sorted[e + 3];
        float4 v0 = __ldg(reinterpret_cast<const float4*>(emb_in + (size_t)(p0 & 0xFFFFu) * C) + lane);
        float4 v1 = __ldg(reinterpret_cast<const float4*>(emb_in + (size_t)(p1 & 0xFFFFu) * C) + lane);
        float4 v2 = __ldg(reinterpret_cast<const float4*>(emb_in + (size_t)(p2 & 0xFFFFu) * C) + lane);
        float4 v3 = __ldg(reinterpret_cast<const float4*>(emb_in + (size_t)(p3 & 0xFFFFu) * C) + lane);
        float4 w0 = wsh[(p0 >> 16) * 32 + lane];
        float4 w1 = wsh[(p1 >> 16) * 32 + lane];
        float4 w2 = wsh[(p2 >> 16) * 32 + lane];
        float4 w3 = wsh[(p3 >> 16) * 32 + lane];
        accA.x += v0.x * w0.x; accA.y += v0.y * w0.y; accA.z += v0.z * w0.z; accA.w += v0.w * w0.w;
        accB.x += v1.x * w1.x; accB.y += v1.y * w1.y; accB.z += v1.z * w1.z; accB.w += v1.w * w1.w;
        accA.x += v2.x * w2.x; accA.y += v2.y * w2.y; accA.z += v2.z * w2.z; accA.w += v2.w * w2.w;
        accB.x += v3.x * w3.x; accB.y += v3.y * w3.y; accB.z += v3.z * w3.z; accB.w += v3.w * w3.w;
    }
    for (; e < end; e++) {
        unsigned p = g_sorted[e];
        float4 v = __ldg(reinterpret_cast<const float4*>(emb_in + (size_t)(p & 0xFFFFu) * C) + lane);
        float4 w = wsh[(p >> 16) * 32 + lane];
        accA.x += v.x * w.x; accA.y += v.y * w.y; accA.z += v.z * w.z; accA.w += v.w * w.w;
    }
    float4 acc = make_float4(accA.x + accB.x, accA.y + accB.y,
                             accA.z + accB.z, accA.w + accB.w);

    // scatter_mean
    float inv_d = 1.0f / fmaxf((float)(end - start), 1.0f);
    acc.x *= inv_d; acc.y *= inv_d; acc.z *= inv_d; acc.w *= inv_d;

    // L2 normalize
    float s = acc.x * acc.x + acc.y * acc.y + acc.z * acc.z + acc.w * acc.w;
    #pragma unroll
    for (int o = 16; o > 0; o >>= 1) s += __shfl_xor_sync(0xffffffff, s, o);
    float inv_n = 1.0f / fmaxf(sqrtf(s), EPS);
    acc.x *= inv_n; acc.y *= inv_n; acc.z *= inv_n; acc.w *= inv_n;

    if (FINAL) {
        // res = base + n1 + n2 + acc  (single fused pass; no emb_out store)
        size_t ro = (size_t)head * C;
        float4 b4 = __ldg(reinterpret_cast<const float4*>(base + ro) + lane);
        float4 a4 = __ldg(reinterpret_cast<const float4*>(n1 + ro) + lane);
        float4 c4 = __ldg(reinterpret_cast<const float4*>(n2 + ro) + lane);
        acc.x += b4.x + a4.x + c4.x;
        acc.y += b4.y + a4.y + c4.y;
        acc.z += b4.z + a4.z + c4.z;
        acc.w += b4.w + a4.w + c4.w;
        reinterpret_cast<float4*>(res + ro)[lane] = acc;
    } else {
        reinterpret_cast<float4*>(emb_out + (size_t)head * C)[lane] = acc;
    }
}

// ---------------------------------------------------------------------------
// kernel_launch
// Inputs: entity_emb f32 [50000,128], edge_index i32 [2,E],
//         edge_type i32 [E], weight f32 [10,128]
// Output: f32 [50000,128]
// ---------------------------------------------------------------------------
extern "C" void kernel_launch(void* const* d_in, const int* in_sizes, int n_in,
                              void* d_out, int out_size) {
    const float* emb = (const float*)d_in[0];
    const int*   ei  = (const int*)d_in[1];
    const int*   et  = (const int*)d_in[2];
    const float* w   = (const float*)d_in[3];
    float* out = (float*)d_out;

    const int E  = in_sizes[1] / 2;
    const int E4 = E / 4;

    void *pA = nullptr, *pB = nullptr, *pC = nullptr;
    cudaGetSymbolAddress(&pA, g_bufA);
    cudaGetSymbolAddress(&pB, g_bufB);
    cudaGetSymbolAddress(&pC, g_cnt);
    float* A = (float*)pA;
    float* B = (float*)pB;

    // ---- Build head-sorted CSR (once; reused by all 3 hops) ----
    cudaMemsetAsync(pC, 0, N_ENT * sizeof(int));
    hist_kernel<<<(E4 + 256) / 256, 256>>>(ei, E4, E);
    tile_sum_kernel<<<NTILE, 256>>>();
    bsum_scan_kernel<<<1, 256>>>();
    tile_scan_kernel<<<NTILE, 256>>>();
    build_kernel<<<(E4 + 256) / 256, 256>>>(ei, et, E4, E);

    // ---- 3 fused hops ----
    const int HOP_BLOCKS = (N_ENT + 7) / 8;   // warp per head, 8 warps/block
    hop_kernel<false><<<HOP_BLOCKS, 256>>>(emb, w, A, nullptr, nullptr, nullptr, nullptr); // n1
    hop_kernel<false><<<HOP_BLOCKS, 256>>>(A,   w, B, nullptr, nullptr, nullptr, nullptr); // n2
    hop_kernel<true ><<<HOP_BLOCKS, 256>>>(B,   w, nullptr, out, emb, A, B);               // res
}

// round 17
// speedup vs baseline: 4.9692x; 1.1600x over previous
#include <cuda_runtime.h>
#include <cuda_fp16.h>

#define N_ENT  50000
#define C      128
#define N_RELM 10              // N_REL - 1
#define EPS    1e-12f
#define NTILE  ((N_ENT + 255) / 256)   // scan tiles (196)

// Scratch (no allocation allowed).
__device__ __half   g_embH[(size_t)N_ENT * C];   // half copy of entity_emb
__device__ __half   g_n1H [(size_t)N_ENT * C];   // hop-1 output (half)
__device__ __half   g_n2H [(size_t)N_ENT * C];   // hop-2 output (half)
__device__ int      g_cnt[N_ENT];
__device__ int      g_fill[N_ENT];
__device__ int      g_off[N_ENT + 1];
__device__ int      g_bsum[NTILE];
__device__ unsigned g_sorted[1600000];           // (tail << 8) | rel   (rel < 10, tail*256 < 2^24)

// ---------------------------------------------------------------------------
// fp32 -> fp16 convert, 4 elems/thread.
// ---------------------------------------------------------------------------
__global__ void cvt_kernel(const float* __restrict__ src, __half* __restrict__ dst, int n4) {
    int i = blockIdx.x * blockDim.x + threadIdx.x;
    if (i >= n4) return;
    float4 v = __ldg(reinterpret_cast<const float4*>(src) + i);
    union { uint2 u; __half2 h[2]; } pk;
    pk.h[0] = __floats2half2_rn(v.x, v.y);
    pk.h[1] = __floats2half2_rn(v.z, v.w);
    reinterpret_cast<uint2*>(dst)[i] = pk.u;
}

// ---------------------------------------------------------------------------
// Histogram of heads, 4 edges per thread (int4) for MLP on the atomics.
// ---------------------------------------------------------------------------
__global__ void hist_kernel(const int* __restrict__ edge_index, int E4, int E) {
    int i = blockIdx.x * blockDim.x + threadIdx.x;
    if (i < E4) {
        int4 h4 = __ldg(reinterpret_cast<const int4*>(edge_index) + i);
        atomicAdd(&g_cnt[h4.x], 1);
        atomicAdd(&g_cnt[h4.y], 1);
        atomicAdd(&g_cnt[h4.z], 1);
        atomicAdd(&g_cnt[h4.w], 1);
    } else if (i == E4) {                 // remainder (E % 4 edges)
        for (int e = E4 * 4; e < E; e++) atomicAdd(&g_cnt[edge_index[e]], 1);
    }
}

// ---------------------------------------------------------------------------
// Parallel scan, step 1: per-tile (256 elems) sums. Coalesced.
// ---------------------------------------------------------------------------
__global__ void tile_sum_kernel() {
    int i = blockIdx.x * 256 + threadIdx.x;
    int v = (i < N_ENT) ? g_cnt[i] : 0;
    #pragma unroll
    for (int o = 16; o > 0; o >>= 1) v += __shfl_xor_sync(0xffffffff, v, o);
    __shared__ int ws[8];
    if ((threadIdx.x & 31) == 0) ws[threadIdx.x >> 5] = v;
    __syncthreads();
    if (threadIdx.x == 0) {
        int s = 0;
        #pragma unroll
        for (int w = 0; w < 8; w++) s += ws[w];
        g_bsum[blockIdx.x] = s;
    }
}

// ---------------------------------------------------------------------------
// Parallel scan, step 2: single block exclusive-scans the NTILE block sums.
// ---------------------------------------------------------------------------
__global__ void bsum_scan_kernel() {
    __shared__ int sh[256];
    int tid = threadIdx.x;
    int v = (tid < NTILE) ? g_bsum[tid] : 0;
    int lane = tid & 31, wid = tid >> 5;
    int x = v;
    #pragma unroll
    for (int o = 1; o < 32; o <<= 1) {
        int y = __shfl_up_sync(0xffffffff, x, o);
        if (lane >= o) x += y;
    }
    __shared__ int ws[8];
    if (lane == 31) ws[wid] = x;
    __syncthreads();
    if (tid == 0) {
        int run = 0;
        #pragma unroll
        for (int w = 0; w < 8; w++) { int t = ws[w]; ws[w] = run; run += t; }
        sh[255] = run;   // total
    }
    __syncthreads();
    int excl = x - v + ws[wid];
    if (tid < NTILE) g_bsum[tid] = excl;
    if (tid == 0) g_off[N_ENT] = sh[255];
}

// ---------------------------------------------------------------------------
// Parallel scan, step 3: per-tile exclusive scan + tile offset -> g_off/g_fill.
// ---------------------------------------------------------------------------
__global__ void tile_scan_kernel() {
    int i = blockIdx.x * 256 + threadIdx.x;
    int v = (i < N_ENT) ? g_cnt[i] : 0;
    int lane = threadIdx.x & 31, wid = threadIdx.x >> 5;
    int x = v;
    #pragma unroll
    for (int o = 1; o < 32; o <<= 1) {
        int y = __shfl_up_sync(0xffffffff, x, o);
        if (lane >= o) x += y;
    }
    __shared__ int ws[8];
    if (lane == 31) ws[wid] = x;
    __syncthreads();
    if (threadIdx.x == 0) {
        int run = 0;
        #pragma unroll
        for (int w = 0; w < 8; w++) { int t = ws[w]; ws[w] = run; run += t; }
    }
    __syncthreads();
    int off = g_bsum[blockIdx.x] + ws[wid] + (x - v);
    if (i < N_ENT) { g_off[i] = off; g_fill[i] = off; }
}

// ---------------------------------------------------------------------------
// Scatter edges into head-sorted order, 4 edges per thread.
// Packs (tail, rel) as (tail << 8) | rel: row byte-offset (half rows = 256 B)
// is p & ~0xFF; weight row index is p & 0xFF.
// ---------------------------------------------------------------------------
__global__ void build_kernel(const int* __restrict__ edge_index,
                             const int* __restrict__ edge_type,
                             int E4, int E) {
    int i = blockIdx.x * blockDim.x + threadIdx.x;
    if (i < E4) {
        int4 h4 = __ldg(reinterpret_cast<const int4*>(edge_index) + i);
        int4 t4 = __ldg(reinterpret_cast<const int4*>(edge_index) + (E >> 2) + i);
        int4 r4 = __ldg(reinterpret_cast<const int4*>(edge_type) + i);
        int p0 = atomicAdd(&g_fill[h4.x], 1);
        int p1 = atomicAdd(&g_fill[h4.y], 1);
        int p2 = atomicAdd(&g_fill[h4.z], 1);
        int p3 = atomicAdd(&g_fill[h4.w], 1);
        g_sorted[p0] = ((unsigned)t4.x << 8) | (unsigned)(r4.x - 1);
        g_sorted[p1] = ((unsigned)t4.y << 8) | (unsigned)(r4.y - 1);
        g_sorted[p2] = ((unsigned)t4.z << 8) | (unsigned)(r4.z - 1);
        g_sorted[p3] = ((unsigned)t4.w << 8) | (unsigned)(r4.w - 1);
    } else if (i == E4) {
        for (int e = E4 * 4; e < E; e++) {
            int h = edge_index[e];
            int p = atomicAdd(&g_fill[h], 1);
            g_sorted[p] = ((unsigned)edge_index[E + e] << 8) |
                          (unsigned)(edge_type[e] - 1);
        }
    }
}

// ---------------------------------------------------------------------------
// One hop: warp per head, no atomics, half gather (256 B rows), fp32 math.
//   acc = mean over segment of emb_in[tail] * weight[rel]; L2-normalize.
//   !FINAL: outH[h] = half(acc)
//   FINAL : res[h] = base[h] + n1[h] + n2[h] + acc   (fp32 out)
// ---------------------------------------------------------------------------
template <bool FINAL>
__global__ void __launch_bounds__(256)
hop_kernel(const __half* __restrict__ embH,
           const float* __restrict__ weight,
           __half* __restrict__ outH,
           float* __restrict__ res,
           const float* __restrict__ base,
           const __half* __restrict__ n1H,
           const __half* __restrict__ n2H) {
    __shared__ float4 wsh[N_RELM * 32];   // 10 relations x 128 ch fp32 = 5 KB
    {
        float* wf = reinterpret_cast<float*>(wsh);
        for (int i = threadIdx.x; i < N_RELM * C; i += 256) wf[i] = weight[i];
    }
    __syncthreads();

    int head = blockIdx.x * 8 + (threadIdx.x >> 5);
    int lane = threadIdx.x & 31;
    if (head >= N_ENT) return;

    int start = g_off[head];
    int end   = g_off[head + 1];

    // per-lane byte base: lane handles 4 halfs = 8 bytes of each 256 B row
    const char* eb = reinterpret_cast<const char*>(embH) + lane * 8;

    float4 accA = make_float4(0.f, 0.f, 0.f, 0.f);
    float4 accB = make_float4(0.f, 0.f, 0.f, 0.f);

    int e = start;
    for (; e + 4 <= end; e += 4) {
        unsigned p0 = g_sorted[e + 0];
        unsigned p1 = g_sorted[e + 1];
        unsigned p2 = g_sorted[e + 2];
        unsigned p3 = g_sorted[e + 3];
        uint2 v0 = __ldg(reinterpret_cast<const uint2*>(eb + (p0 & 0xFFFFFF00u)));
        uint2 v1 = __ldg(reinterpret_cast<const uint2*>(eb + (p1 & 0xFFFFFF00u)));
        uint2 v2 = __ldg(reinterpret_cast<const uint2*>(eb + (p2 & 0xFFFFFF00u)));
        uint2 v3 = __ldg(reinterpret_cast<const uint2*>(eb + (p3 & 0xFFFFFF00u)));
        float4 w0 = wsh[(p0 & 0xFFu) * 32 + lane];
        float4 w1 = wsh[(p1 & 0xFFu) * 32 + lane];
        float4 w2 = wsh[(p2 & 0xFFu) * 32 + lane];
        float4 w3 = wsh[(p3 & 0xFFu) * 32 + lane];
        {
            float2 lo = __half22float2(*reinterpret_cast<__half2*>(&v0.x));
            float2 hi = __half22float2(*reinterpret_cast<__half2*>(&v0.y));
            accA.x += lo.x * w0.x; accA.y += lo.y * w0.y;
            accA.z += hi.x * w0.z; accA.w += hi.y * w0.w;
        }
        {
            float2 lo = __half22float2(*reinterpret_cast<__half2*>(&v1.x));
            float2 hi = __half22float2(*reinterpret_cast<__half2*>(&v1.y));
            accB.x += lo.x * w1.x; accB.y += lo.y * w1.y;
            accB.z += hi.x * w1.z; accB.w += hi.y * w1.w;
        }
        {
            float2 lo = __half22float2(*reinterpret_cast<__half2*>(&v2.x));
            float2 hi = __half22float2(*reinterpret_cast<__half2*>(&v2.y));
            accA.x += lo.x * w2.x; accA.y += lo.y * w2.y;
            accA.z += hi.x * w2.z; accA.w += hi.y * w2.w;
        }
        {
            float2 lo = __half22float2(*reinterpret_cast<__half2*>(&v3.x));
            float2 hi = __half22float2(*reinterpret_cast<__half2*>(&v3.y));
            accB.x += lo.x * w3.x; accB.y += lo.y * w3.y;
            accB.z += hi.x * w3.z; accB.w += hi.y * w3.w;
        }
    }
    for (; e < end; e++) {
        unsigned p = g_sorted[e];
        uint2 v = __ldg(reinterpret_cast<const uint2*>(eb + (p & 0xFFFFFF00u)));
        float4 w = wsh[(p & 0xFFu) * 32 + lane];
        float2 lo = __half22float2(*reinterpret_cast<__half2*>(&v.x));
        float2 hi = __half22float2(*reinterpret_cast<__half2*>(&v.y));
        accA.x += lo.x * w.x; accA.y += lo.y * w.y;
        accA.z += hi.x * w.z; accA.w += hi.y * w.w;
    }
    float4 acc = make_float4(accA.x + accB.x, accA.y + accB.y,
                             accA.z + accB.z, accA.w + accB.w);

    // scatter_mean
    float inv_d = 1.0f / fmaxf((float)(end - start), 1.0f);
    acc.x *= inv_d; acc.y *= inv_d; acc.z *= inv_d; acc.w *= inv_d;

    // L2 normalize
    float s = acc.x * acc.x + acc.y * acc.y + acc.z * acc.z + acc.w * acc.w;
    #pragma unroll
    for (int o = 16; o > 0; o >>= 1) s += __shfl_xor_sync(0xffffffff, s, o);
    float inv_n = 1.0f / fmaxf(sqrtf(s), EPS);
    acc.x *= inv_n; acc.y *= inv_n; acc.z *= inv_n; acc.w *= inv_n;

    size_t ro = (size_t)head * C;
    if (FINAL) {
        // res = base + n1 + n2 + acc  (fp32 output, fp32 base, half n1/n2)
        float4 b4 = __ldg(reinterpret_cast<const float4*>(base + ro) + lane);
        uint2 u1 = __ldg(reinterpret_cast<const uint2*>(n1H + ro) + lane);
        uint2 u2 = __ldg(reinterpret_cast<const uint2*>(n2H + ro) + lane);
        float2 a0 = __half22float2(*reinterpret_cast<__half2*>(&u1.x));
        float2 a1 = __half22float2(*reinterpret_cast<__half2*>(&u1.y));
        float2 c0 = __half22float2(*reinterpret_cast<__half2*>(&u2.x));
        float2 c1 = __half22float2(*reinterpret_cast<__half2*>(&u2.y));
        acc.x += b4.x + a0.x + c0.x;
        acc.y += b4.y + a0.y + c0.y;
        acc.z += b4.z + a1.x + c1.x;
        acc.w += b4.w + a1.y + c1.y;
        reinterpret_cast<float4*>(res + ro)[lane] = acc;
    } else {
        union { uint2 u; __half2 h[2]; } pk;
        pk.h[0] = __floats2half2_rn(acc.x, acc.y);
        pk.h[1] = __floats2half2_rn(acc.z, acc.w);
        reinterpret_cast<uint2*>(outH + ro)[lane] = pk.u;
    }
}

// ---------------------------------------------------------------------------
// kernel_launch
// Inputs: entity_emb f32 [50000,128], edge_index i32 [2,E],
//         edge_type i32 [E], weight f32 [10,128]
// Output: f32 [50000,128]
// ---------------------------------------------------------------------------
extern "C" void kernel_launch(void* const* d_in, const int* in_sizes, int n_in,
                              void* d_out, int out_size) {
    const float* emb = (const float*)d_in[0];
    const int*   ei  = (const int*)d_in[1];
    const int*   et  = (const int*)d_in[2];
    const float* w   = (const float*)d_in[3];
    float* out = (float*)d_out;

    const int E  = in_sizes[1] / 2;
    const int E4 = E / 4;
    const int NH4 = N_ENT * C / 4;

    void *pE = nullptr, *p1 = nullptr, *p2 = nullptr, *pC = nullptr;
    cudaGetSymbolAddress(&pE, g_embH);
    cudaGetSymbolAddress(&p1, g_n1H);
    cudaGetSymbolAddress(&p2, g_n2H);
    cudaGetSymbolAddress(&pC, g_cnt);
    __half* embH = (__half*)pE;
    __half* n1H  = (__half*)p1;
    __half* n2H  = (__half*)p2;

    // ---- entity_emb -> half ----
    cvt_kernel<<<(NH4 + 255) / 256, 256>>>(emb, embH, NH4);

    // ---- Build head-sorted CSR (once; reused by all 3 hops) ----
    cudaMemsetAsync(pC, 0, N_ENT * sizeof(int));
    hist_kernel<<<(E4 + 256) / 256, 256>>>(ei, E4, E);
    tile_sum_kernel<<<NTILE, 256>>>();
    bsum_scan_kernel<<<1, 256>>>();
    tile_scan_kernel<<<NTILE, 256>>>();
    build_kernel<<<(E4 + 256) / 256, 256>>>(ei, et, E4, E);

    // ---- 3 fused hops ----
    const int HOP_BLOCKS = (N_ENT + 7) / 8;   // warp per head, 8 warps/block
    hop_kernel<false><<<HOP_BLOCKS, 256>>>(embH, w, n1H, nullptr, nullptr, nullptr, nullptr);
    hop_kernel<false><<<HOP_BLOCKS, 256>>>(n1H,  w, n2H, nullptr, nullptr, nullptr, nullptr);
    hop_kernel<true ><<<HOP_BLOCKS, 256>>>(n2H,  w, nullptr, out, emb, n1H, n2H);
}